// round 14
// baseline (speedup 1.0000x reference)
#include <cuda_runtime.h>
#include <cstdint>

#define Rn 786432      // B*N*P
#define Mn 24576       // B*N

// ---------------- scratch (static device globals; no allocation) ----------------
__device__ float g_h1[Rn * 64];
__device__ float g_pool2[Mn * 64];       // masked max over P of raw layer-2 output
__device__ unsigned char g_m8[Rn];
__device__ unsigned char g_valid[Mn];
__device__ float g_sum[3 * 64];
__device__ float g_sq[3 * 64];
__device__ int   g_cnt;
__device__ int   g_mode;   // 0=u8 bool, 1=int32, 2=float32

// packed-pair FMA: acc(f32x2) += {a,a} * w(f32x2)
__device__ __forceinline__ void fma2(float2 &acc, float a, float2 w) {
    float2 a2 = make_float2(a, a);
    asm("fma.rn.f32x2 %0, %1, %2, %0;"
        : "+l"(reinterpret_cast<unsigned long long &>(acc))
        : "l"(reinterpret_cast<unsigned long long &>(a2)),
          "l"(reinterpret_cast<unsigned long long &>(w)));
}

// ---------------- K0: zero accumulators + detect mask dtype ----------------
__global__ void k_init(const unsigned char *__restrict__ mraw) {
    int t = threadIdx.x;
    if (t < 192) { g_sum[t] = 0.f; g_sq[t] = 0.f; }
    if (t == 0) g_cnt = 0;
    __shared__ int fNB, fMis;
    if (t == 0) { fNB = 0; fMis = 0; }
    __syncthreads();
    for (int i = t; i < 1024; i += 256) {
        uchar4 v = reinterpret_cast<const uchar4 *>(mraw)[i];
        if ((v.x > 1) | (v.y > 1) | (v.z > 1) | (v.w > 1)) atomicOr(&fNB, 1);
        if ((v.y != 0) | (v.z != 0) | (v.w != 0)) atomicOr(&fMis, 1);
    }
    __syncthreads();
    if (t == 0) g_mode = fNB ? 2 : (fMis ? 0 : 1);
}

// ---------------- K1: mask pack + pre GEMM (C=9 -> H=64) + BN0 stats (scalar; measured 67us) ----------------
__global__ void __launch_bounds__(256) k_pre(const float *__restrict__ x,
                                             const float *__restrict__ Wp,
                                             const void *__restrict__ mraw) {
    __shared__ float xs[128 * 9];
    __shared__ float wp[576];
    __shared__ float msx[128];
    __shared__ float red[512];
    __shared__ int cw[4];
    int t = threadIdx.x;
    int r0 = blockIdx.x * 128;

    int bit = 0;
    if (t < 128) {
        int r = r0 + t;
        int mode = g_mode;
        if (mode == 0)      bit = reinterpret_cast<const unsigned char *>(mraw)[r] != 0;
        else if (mode == 1) bit = reinterpret_cast<const int *>(mraw)[r] != 0;
        else                bit = reinterpret_cast<const float *>(mraw)[r] != 0.f;
        g_m8[r] = (unsigned char)bit;
        msx[t] = (float)bit;
    }
    unsigned bal = __ballot_sync(0xffffffffu, bit);
    if (t < 128 && (t & 31) == 0) {
        g_valid[blockIdx.x * 4 + (t >> 5)] = bal ? 1 : 0;
        cw[t >> 5] = __popc(bal);
    }
    for (int i = t; i < 1152; i += 256) xs[i] = x[(size_t)r0 * 9 + i];
    for (int i = t; i < 576; i += 256) wp[i] = Wp[i];
    __syncthreads();
    if (t == 0) atomicAdd(&g_cnt, cw[0] + cw[1] + cw[2] + cw[3]);

    int j = t & 63, g = t >> 6;
    float s = 0.f, ss = 0.f;
    for (int lr = g * 32; lr < g * 32 + 32; lr++) {
        float h = 0.f;
#pragma unroll
        for (int c = 0; c < 9; c++) h = fmaf(xs[lr * 9 + c], wp[j * 9 + c], h);
        float m = msx[lr];
        s = fmaf(m, h, s);
        ss = fmaf(m * h, h, ss);
    }
    red[j * 4 + g] = s;
    red[256 + j * 4 + g] = ss;
    __syncthreads();
    if (t < 64) {
        float S  = red[t * 4] + red[t * 4 + 1] + red[t * 4 + 2] + red[t * 4 + 3];
        float SS = red[256 + t * 4] + red[256 + t * 4 + 1] + red[256 + t * 4 + 2] + red[256 + t * 4 + 3];
        atomicAdd(&g_sum[t], S);
        atomicAdd(&g_sq[t], SS);
    }
}

// ---------------- K2: layer1 (R11 exact: measured form + inline fin0) ----------------
__global__ void __launch_bounds__(256) k_mlp1(const float *__restrict__ x,
                                              const float *__restrict__ Wp,
                                              const float *__restrict__ gpre,
                                              const float *__restrict__ bpre,
                                              const float *__restrict__ W) {
    extern __shared__ float sm[];
    float *As = sm;                  // [128][68] = 8704
    float *Wa = sm + 8704;           // [64][68] = 4352 (aliased by xs/wpT in stage0)
    float *Wb = Wa + 4352;           // [64][68] = 4352
    float *pooledS = Wb + 4352;      // 256
    float *pcS = pooledS + 256;      // 256
    float *ms = pcS + 256;           // 128
    float *aS = ms + 128;            // 64
    float *bS = aS + 64;             // 64
    float *xs = Wa;                  // 1536 (alias)
    float *wpT = Wa + 1536;          // 576  (alias)

    int t = threadIdx.x;
    int r0 = blockIdx.x * 128;
    int p = t & 31;
    int h0 = (t >> 5) << 3;

    if (t < 128) ms[t] = (float)g_m8[r0 + t];
    if (t < 64) {   // inline fin0 from g_sum/g_sq
        float cnt = (float)g_cnt;
        float mean = g_sum[t] / cnt;
        float var = fmaxf(g_sq[t] / cnt - mean * mean, 0.f);
        float a = gpre[t] * rsqrtf(var + 1e-5f);
        aS[t] = a;
        bS[t] = bpre[t] - mean * a;
    }
    for (int idx = t; idx < 1152; idx += 256) {
        int row = idx / 9, c = idx - row * 9;
        xs[row * 12 + c] = x[(size_t)r0 * 9 + idx];
    }
    for (int idx = t; idx < 576; idx += 256) {
        int h = idx / 9, c = idx - h * 9;
        wpT[c * 64 + h] = Wp[idx];
    }
    __syncthreads();

    // recompute pre-layer into registers (vectorized), then BN0+ReLU+mask -> As
    {
        float2 acc[4][4];
#pragma unroll
        for (int q = 0; q < 4; q++)
#pragma unroll
            for (int j = 0; j < 4; j++) acc[q][j] = make_float2(0.f, 0.f);
#pragma unroll
        for (int qp = 0; qp < 2; qp++) {
            float4 ar[2][3];
#pragma unroll
            for (int s = 0; s < 2; s++) {
                int row = (qp * 2 + s) * 32 + p;
#pragma unroll
                for (int j = 0; j < 3; j++)
                    ar[s][j] = *reinterpret_cast<const float4 *>(&xs[row * 12 + 4 * j]);
            }
#pragma unroll
            for (int c = 0; c < 9; c++) {
                float4 wlo = *reinterpret_cast<const float4 *>(&wpT[c * 64 + h0]);
                float4 whi = *reinterpret_cast<const float4 *>(&wpT[c * 64 + h0 + 4]);
                float2 w0 = make_float2(wlo.x, wlo.y);
                float2 w1 = make_float2(wlo.z, wlo.w);
                float2 w2 = make_float2(whi.x, whi.y);
                float2 w3 = make_float2(whi.z, whi.w);
#pragma unroll
                for (int s = 0; s < 2; s++) {
                    float a = reinterpret_cast<const float *>(&ar[s][0])[c];
                    fma2(acc[qp * 2 + s][0], a, w0);
                    fma2(acc[qp * 2 + s][1], a, w1);
                    fma2(acc[qp * 2 + s][2], a, w2);
                    fma2(acc[qp * 2 + s][3], a, w3);
                }
            }
        }
        float av[8], bv[8];
#pragma unroll
        for (int i = 0; i < 8; i++) { av[i] = aS[h0 + i]; bv[i] = bS[h0 + i]; }
#pragma unroll
        for (int q = 0; q < 4; q++) {
            int row = q * 32 + p;
            float m = ms[row];
            float v[8];
#pragma unroll
            for (int i = 0; i < 8; i++) {
                float h = (i & 1) ? acc[q][i >> 1].y : acc[q][i >> 1].x;
                v[i] = fmaxf(fmaf(h, av[i], bv[i]), 0.f) * m;
            }
            *reinterpret_cast<float4 *>(&As[row * 68 + h0]) = make_float4(v[0], v[1], v[2], v[3]);
            *reinterpret_cast<float4 *>(&As[row * 68 + h0 + 4]) = make_float4(v[4], v[5], v[6], v[7]);
        }
    }
    __syncthreads();

    // load W1 transposed (coalesced gmem; one-shot STS conflicts absorbed)
    for (int idx = t; idx < 8192; idx += 256) {
        float v = W[idx];
        int h = idx >> 7, k2 = idx & 127;
        if (k2 < 64) Wa[k2 * 68 + h] = v;
        else Wb[(k2 - 64) * 68 + h] = v;
    }
    __syncthreads();

    // maxpool over P (values >=0; invalid rows exact zeros)
    {
        int q = t >> 6, k = t & 63;
        float mx = 0.f;
        for (int pp = 0; pp < 32; pp++) mx = fmaxf(mx, As[(q * 32 + pp) * 68 + k]);
        pooledS[q * 64 + k] = mx;
    }
    __syncthreads();
    // pooled contribution: pc[q][h] = sum_k pooled[q][k] * W[h][64+k]
    {
        int q = t >> 6, h = t & 63;
        float acc = 0.f;
        for (int k = 0; k < 64; k++) acc = fmaf(pooledS[q * 64 + k], Wb[k * 68 + h], acc);
        pcS[q * 64 + h] = acc;
    }
    __syncthreads();

    // GEMM: per thread -> 4 polylines x 8 channels
    float2 acc[4][4];
#pragma unroll
    for (int q = 0; q < 4; q++)
#pragma unroll
        for (int j = 0; j < 4; j++) acc[q][j] = make_float2(0.f, 0.f);

    for (int k = 0; k < 64; k += 4) {
        float av[4][4];
#pragma unroll
        for (int q = 0; q < 4; q++) {
            float4 tmp = *reinterpret_cast<const float4 *>(&As[(q * 32 + p) * 68 + k]);
            av[q][0] = tmp.x; av[q][1] = tmp.y; av[q][2] = tmp.z; av[q][3] = tmp.w;
        }
#pragma unroll
        for (int kk = 0; kk < 4; kk++) {
            const float *wr = &Wa[(k + kk) * 68 + h0];
            float4 wlo = *reinterpret_cast<const float4 *>(wr);
            float4 whi = *reinterpret_cast<const float4 *>(wr + 4);
            float2 w0 = make_float2(wlo.x, wlo.y);
            float2 w1 = make_float2(wlo.z, wlo.w);
            float2 w2 = make_float2(whi.x, whi.y);
            float2 w3 = make_float2(whi.z, whi.w);
#pragma unroll
            for (int q = 0; q < 4; q++) {
                float a = av[q][kk];
                fma2(acc[q][0], a, w0);
                fma2(acc[q][1], a, w1);
                fma2(acc[q][2], a, w2);
                fma2(acc[q][3], a, w3);
            }
        }
    }

    float vfin[4][8];
#pragma unroll
    for (int q = 0; q < 4; q++) {
#pragma unroll
        for (int j = 0; j < 4; j++) {
            vfin[q][2 * j]     = acc[q][j].x + pcS[q * 64 + h0 + 2 * j];
            vfin[q][2 * j + 1] = acc[q][j].y + pcS[q * 64 + h0 + 2 * j + 1];
        }
        size_t base = ((size_t)(r0 + q * 32 + p)) * 64 + h0;
        *reinterpret_cast<float4 *>(&g_h1[base]) =
            make_float4(vfin[q][0], vfin[q][1], vfin[q][2], vfin[q][3]);
        *reinterpret_cast<float4 *>(&g_h1[base + 4]) =
            make_float4(vfin[q][4], vfin[q][5], vfin[q][6], vfin[q][7]);
    }
    float mq[4];
#pragma unroll
    for (int q = 0; q < 4; q++) mq[q] = ms[q * 32 + p];
#pragma unroll
    for (int i = 0; i < 8; i++) {
        float s = 0.f, ss = 0.f;
#pragma unroll
        for (int q = 0; q < 4; q++) {
            float v = vfin[q][i];
            s = fmaf(mq[q], v, s);
            ss = fmaf(mq[q] * v, v, ss);
        }
#pragma unroll
        for (int off = 16; off > 0; off >>= 1) {
            s += __shfl_xor_sync(0xffffffffu, s, off);
            ss += __shfl_xor_sync(0xffffffffu, ss, off);
        }
        if (p == 0) {
            atomicAdd(&g_sum[64 + h0 + i], s);
            atomicAdd(&g_sq[64 + h0 + i], ss);
        }
    }
}

// ---------------- K3 (PROFILED @ idx 3): layer2 v2 — 256-row block, 4x16 register tile ----------------
// warp w: covers rows [128*(w>>2), +128), channels [16*(w&3), +16)
// thread: 4 rows of ONE polyline (grp = p>>3, lp = p&7) x 16 channels
__global__ void __launch_bounds__(256) k_mlp2(const float *__restrict__ g1v,
                                              const float *__restrict__ b1v,
                                              const float *__restrict__ W) {
    extern __shared__ float sm[];
    float *As = sm;                  // [256][68] = 17408
    float *Wa = sm + 17408;          // [64][68]  = 4352 (padded: 4-way STS at stage)
    float *ms = sm + 21760;          // 256
    float *aS = sm + 22016;          // 64
    float *bS = sm + 22080;          // 64  -> 22144 floats = 88576 B

    int t = threadIdx.x;
    int wid = t >> 5;
    int p = t & 31;
    int r0 = blockIdx.x * 256;
    int h0 = (wid & 3) * 16;
    int rhalf = wid >> 2;            // 0/1: which 128-row half
    int grp = p >> 3, lp = p & 7;

    if (t < 256) ms[t] = (float)g_m8[r0 + t];
    if (t < 64) {   // inline fin1
        float cnt = (float)g_cnt;
        float mean = g_sum[64 + t] / cnt;
        float var = fmaxf(g_sq[64 + t] / cnt - mean * mean, 0.f);
        float a = g1v[t] * rsqrtf(var + 1e-5f);
        aS[t] = a;
        bS[t] = b1v[t] - mean * a;
    }
    // W2 transpose: coalesced LDG; STS stride-68 -> 4-way conflict only
    for (int idx = t; idx < 4096; idx += 256) {
        int h = idx >> 6, k2 = idx & 63;
        Wa[k2 * 68 + h] = W[idx];
    }
    __syncthreads();

    const float4 *hin4 = reinterpret_cast<const float4 *>(g_h1 + (size_t)r0 * 64);
    for (int i4 = t; i4 < 4096; i4 += 256) {
        float4 v = hin4[i4];
        int row = i4 >> 4;
        int kq = (i4 & 15) << 2;
        float m = ms[row];
        v.x = fmaxf(fmaf(v.x, aS[kq + 0], bS[kq + 0]), 0.f) * m;
        v.y = fmaxf(fmaf(v.y, aS[kq + 1], bS[kq + 1]), 0.f) * m;
        v.z = fmaxf(fmaf(v.z, aS[kq + 2], bS[kq + 2]), 0.f) * m;
        v.w = fmaxf(fmaf(v.w, aS[kq + 3], bS[kq + 3]), 0.f) * m;
        *reinterpret_cast<float4 *>(&As[(size_t)row * 68 + kq]) = v;
    }
    __syncthreads();

    int rowB[4];
#pragma unroll
    for (int q = 0; q < 4; q++) rowB[q] = rhalf * 128 + grp * 32 + 8 * q + lp;

    float2 acc[4][8];
#pragma unroll
    for (int q = 0; q < 4; q++)
#pragma unroll
        for (int j = 0; j < 8; j++) acc[q][j] = make_float2(0.f, 0.f);

    for (int k = 0; k < 64; k += 4) {
        float av[4][4];
#pragma unroll
        for (int q = 0; q < 4; q++) {
            float4 tmp = *reinterpret_cast<const float4 *>(&As[rowB[q] * 68 + k]);
            av[q][0] = tmp.x; av[q][1] = tmp.y; av[q][2] = tmp.z; av[q][3] = tmp.w;
        }
#pragma unroll
        for (int kk = 0; kk < 4; kk++) {
            const float *wr = &Wa[(k + kk) * 68 + h0];
            float4 wA = *reinterpret_cast<const float4 *>(wr);
            float4 wB = *reinterpret_cast<const float4 *>(wr + 4);
            float4 wC = *reinterpret_cast<const float4 *>(wr + 8);
            float4 wD = *reinterpret_cast<const float4 *>(wr + 12);
            float2 w0 = make_float2(wA.x, wA.y);
            float2 w1 = make_float2(wA.z, wA.w);
            float2 w2 = make_float2(wB.x, wB.y);
            float2 w3 = make_float2(wB.z, wB.w);
            float2 w4 = make_float2(wC.x, wC.y);
            float2 w5 = make_float2(wC.z, wC.w);
            float2 w6 = make_float2(wD.x, wD.y);
            float2 w7 = make_float2(wD.z, wD.w);
#pragma unroll
            for (int q = 0; q < 4; q++) {
                float a = av[q][kk];
                fma2(acc[q][0], a, w0);
                fma2(acc[q][1], a, w1);
                fma2(acc[q][2], a, w2);
                fma2(acc[q][3], a, w3);
                fma2(acc[q][4], a, w4);
                fma2(acc[q][5], a, w5);
                fma2(acc[q][6], a, w6);
                fma2(acc[q][7], a, w7);
            }
        }
    }

    // epilogue: BN2 stats + masked max over the polyline (in-thread + 3 shuffles)
    float mq[4];
#pragma unroll
    for (int q = 0; q < 4; q++) mq[q] = ms[rowB[q]];

    float mxv[16];
#pragma unroll
    for (int i = 0; i < 16; i++) mxv[i] = -3.4e38f;

#pragma unroll
    for (int i = 0; i < 16; i++) {
        float s = 0.f, ss = 0.f;
#pragma unroll
        for (int q = 0; q < 4; q++) {
            float v = (i & 1) ? acc[q][i >> 1].y : acc[q][i >> 1].x;
            s = fmaf(mq[q], v, s);
            ss = fmaf(mq[q] * v, v, ss);
            float cand = (mq[q] > 0.f) ? v : -3.4e38f;
            mxv[i] = fmaxf(mxv[i], cand);
        }
#pragma unroll
        for (int off = 16; off > 0; off >>= 1) {
            s += __shfl_xor_sync(0xffffffffu, s, off);
            ss += __shfl_xor_sync(0xffffffffu, ss, off);
        }
        if (p == 0) {
            atomicAdd(&g_sum[128 + h0 + i], s);
            atomicAdd(&g_sq[128 + h0 + i], ss);
        }
    }
#pragma unroll
    for (int i = 0; i < 16; i++) {
#pragma unroll
        for (int d = 1; d < 8; d <<= 1)
            mxv[i] = fmaxf(mxv[i], __shfl_xor_sync(0xffffffffu, mxv[i], d));
    }
    if (lp == 0) {
        // polyline id for this thread's 8-lane group
        size_t base = (size_t)(blockIdx.x * 8 + rhalf * 4 + grp) * 64 + h0;
        *reinterpret_cast<float4 *>(&g_pool2[base])      = make_float4(mxv[0], mxv[1], mxv[2], mxv[3]);
        *reinterpret_cast<float4 *>(&g_pool2[base + 4])  = make_float4(mxv[4], mxv[5], mxv[6], mxv[7]);
        *reinterpret_cast<float4 *>(&g_pool2[base + 8])  = make_float4(mxv[8], mxv[9], mxv[10], mxv[11]);
        *reinterpret_cast<float4 *>(&g_pool2[base + 12]) = make_float4(mxv[12], mxv[13], mxv[14], mxv[15]);
    }
}

// ---------------- K4: blocked out-MLP (R11 exact) ----------------
__global__ void __launch_bounds__(256) k_out(const float *__restrict__ g2,
                                             const float *__restrict__ b2v,
                                             const float *__restrict__ Wo1,
                                             const float *__restrict__ bo1,
                                             const float *__restrict__ Wo2,
                                             const float *__restrict__ bo2,
                                             float *__restrict__ out) {
    extern __shared__ float sm[];
    float *poolS = sm;            // [128][68] = 8704
    float *y1S = sm + 8704;       // [128][68] = 8704
    float *W1T = sm + 17408;      // [64][64]  = 4096
    float *W2T = sm + 21504;      // [64][128] = 8192
    float *bo1S = sm + 29696;     // 64
    float *bo2S = sm + 29760;     // 128
    float *aS = sm + 29888;       // 64
    float *bS = sm + 29952;       // 64   -> 30016 floats = 120064 B

    int t = threadIdx.x;
    int p = t & 31;
    int h0 = (t >> 5) << 3;

    if (t < 64) {
        float cnt = (float)g_cnt;
        float mean = g_sum[128 + t] / cnt;
        float var = fmaxf(g_sq[128 + t] / cnt - mean * mean, 0.f);
        float a = g2[t] * rsqrtf(var + 1e-5f);
        aS[t] = a;
        bS[t] = b2v[t] - mean * a;
        bo1S[t] = bo1[t];
    }
    if (t < 128) bo2S[t] = bo2[t];
    for (int idx = t; idx < 4096; idx += 256) {
        int h = idx >> 6, k = idx & 63;
        W1T[k * 64 + h] = Wo1[idx];
    }
    for (int idx = t; idx < 8192; idx += 256) {
        int o = idx >> 6, k = idx & 63;
        W2T[k * 128 + o] = Wo2[idx];
    }
    __syncthreads();

    for (int tile = 0; tile < 2; tile++) {
        int bn0 = (blockIdx.x * 2 + tile) * 128;
        const float4 *p4 = reinterpret_cast<const float4 *>(g_pool2 + (size_t)bn0 * 64);
        for (int i4 = t; i4 < 2048; i4 += 256) {
            float4 v = p4[i4];
            int row = i4 >> 4, c = (i4 & 15) << 2;
            v.x = fmaxf(fmaf(v.x, aS[c + 0], bS[c + 0]), 0.f);
            v.y = fmaxf(fmaf(v.y, aS[c + 1], bS[c + 1]), 0.f);
            v.z = fmaxf(fmaf(v.z, aS[c + 2], bS[c + 2]), 0.f);
            v.w = fmaxf(fmaf(v.w, aS[c + 3], bS[c + 3]), 0.f);
            *reinterpret_cast<float4 *>(&poolS[row * 68 + c]) = v;
        }
        __syncthreads();

        // y1 = relu(pool @ Wo1^T + bo1)
        {
            float2 acc[4][4];
#pragma unroll
            for (int q = 0; q < 4; q++)
#pragma unroll
                for (int j = 0; j < 4; j++) acc[q][j] = make_float2(0.f, 0.f);
#pragma unroll
            for (int k = 0; k < 64; k += 4) {
                float av[4][4];
#pragma unroll
                for (int q = 0; q < 4; q++) {
                    float4 tmp = *reinterpret_cast<const float4 *>(&poolS[(q * 32 + p) * 68 + k]);
                    av[q][0] = tmp.x; av[q][1] = tmp.y; av[q][2] = tmp.z; av[q][3] = tmp.w;
                }
#pragma unroll
                for (int kk = 0; kk < 4; kk++) {
                    float4 wlo = *reinterpret_cast<const float4 *>(&W1T[(k + kk) * 64 + h0]);
                    float4 whi = *reinterpret_cast<const float4 *>(&W1T[(k + kk) * 64 + h0 + 4]);
                    float2 w0 = make_float2(wlo.x, wlo.y);
                    float2 w1 = make_float2(wlo.z, wlo.w);
                    float2 w2 = make_float2(whi.x, whi.y);
                    float2 w3 = make_float2(whi.z, whi.w);
#pragma unroll
                    for (int q = 0; q < 4; q++) {
                        float a = av[q][kk];
                        fma2(acc[q][0], a, w0);
                        fma2(acc[q][1], a, w1);
                        fma2(acc[q][2], a, w2);
                        fma2(acc[q][3], a, w3);
                    }
                }
            }
#pragma unroll
            for (int q = 0; q < 4; q++) {
                int row = q * 32 + p;
                float v[8];
#pragma unroll
                for (int i = 0; i < 8; i++) {
                    float hv = (i & 1) ? acc[q][i >> 1].y : acc[q][i >> 1].x;
                    v[i] = fmaxf(hv + bo1S[h0 + i], 0.f);
                }
                *reinterpret_cast<float4 *>(&y1S[row * 68 + h0]) = make_float4(v[0], v[1], v[2], v[3]);
                *reinterpret_cast<float4 *>(&y1S[row * 68 + h0 + 4]) = make_float4(v[4], v[5], v[6], v[7]);
            }
        }
        __syncthreads();

        // y2 = (y1 @ Wo2^T + bo2) * valid
#pragma unroll
        for (int half = 0; half < 2; half++) {
            int o0 = h0 + 64 * half;
            float2 acc[4][4];
#pragma unroll
            for (int q = 0; q < 4; q++)
#pragma unroll
                for (int j = 0; j < 4; j++) acc[q][j] = make_float2(0.f, 0.f);
#pragma unroll
            for (int k = 0; k < 64; k += 4) {
                float av[4][4];
#pragma unroll
                for (int q = 0; q < 4; q++) {
                    float4 tmp = *reinterpret_cast<const float4 *>(&y1S[(q * 32 + p) * 68 + k]);
                    av[q][0] = tmp.x; av[q][1] = tmp.y; av[q][2] = tmp.z; av[q][3] = tmp.w;
                }
#pragma unroll
                for (int kk = 0; kk < 4; kk++) {
                    float4 wlo = *reinterpret_cast<const float4 *>(&W2T[(k + kk) * 128 + o0]);
                    float4 whi = *reinterpret_cast<const float4 *>(&W2T[(k + kk) * 128 + o0 + 4]);
                    float2 w0 = make_float2(wlo.x, wlo.y);
                    float2 w1 = make_float2(wlo.z, wlo.w);
                    float2 w2 = make_float2(whi.x, whi.y);
                    float2 w3 = make_float2(whi.z, whi.w);
#pragma unroll
                    for (int q = 0; q < 4; q++) {
                        float a = av[q][kk];
                        fma2(acc[q][0], a, w0);
                        fma2(acc[q][1], a, w1);
                        fma2(acc[q][2], a, w2);
                        fma2(acc[q][3], a, w3);
                    }
                }
            }
#pragma unroll
            for (int q = 0; q < 4; q++) {
                int row = q * 32 + p;
                float vf = g_valid[bn0 + row] ? 1.f : 0.f;
                float v[8];
#pragma unroll
                for (int i = 0; i < 8; i++) {
                    float hv = (i & 1) ? acc[q][i >> 1].y : acc[q][i >> 1].x;
                    v[i] = (hv + bo2S[o0 + i]) * vf;
                }
                size_t base = (size_t)(bn0 + row) * 128 + o0;
                *reinterpret_cast<float4 *>(&out[base]) = make_float4(v[0], v[1], v[2], v[3]);
                *reinterpret_cast<float4 *>(&out[base + 4]) = make_float4(v[4], v[5], v[6], v[7]);
            }
        }
        __syncthreads();
    }
}

// ---------------- launcher ----------------
extern "C" void kernel_launch(void *const *d_in, const int *in_sizes, int n_in,
                              void *d_out, int out_size) {
    const float *poly = (const float *)d_in[0];
    const void *mask = d_in[1];
    const float *Wpre = (const float *)d_in[2];
    const float *gpre = (const float *)d_in[3];
    const float *bpre = (const float *)d_in[4];
    const float *W1 = (const float *)d_in[5];
    const float *g1 = (const float *)d_in[6];
    const float *b1 = (const float *)d_in[7];
    const float *W2 = (const float *)d_in[8];
    const float *g2 = (const float *)d_in[9];
    const float *b2 = (const float *)d_in[10];
    const float *Wo1 = (const float *)d_in[11];
    const float *bo1 = (const float *)d_in[12];
    const float *Wo2 = (const float *)d_in[13];
    const float *bo2 = (const float *)d_in[14];
    float *out = (float *)d_out;

    cudaFuncSetAttribute(k_mlp1, cudaFuncAttributeMaxDynamicSharedMemorySize, 72704);
    cudaFuncSetAttribute(k_mlp2, cudaFuncAttributeMaxDynamicSharedMemorySize, 88576);
    cudaFuncSetAttribute(k_out,  cudaFuncAttributeMaxDynamicSharedMemorySize, 120064);

    k_init<<<1, 256>>>((const unsigned char *)mask);                 // idx 0
    k_pre<<<6144, 256>>>(poly, Wpre, mask);                          // idx 1
    k_mlp1<<<6144, 256, 72704>>>(poly, Wpre, gpre, bpre, W1);        // idx 2
    k_mlp2<<<3072, 256, 88576>>>(g1, b1, W2);                        // idx 3  <- profiled
    k_out<<<96, 256, 120064>>>(g2, b2, Wo1, bo1, Wo2, bo2, out);     // idx 4
}

// round 15
// speedup vs baseline: 1.0652x; 1.0652x over previous
#include <cuda_runtime.h>
#include <cuda_fp16.h>
#include <cstdint>

#define Rn 786432      // B*N*P
#define Mn 24576       // B*N

// ---------------- scratch (static device globals; no allocation) ----------------
__device__ __half g_h1[Rn * 64];         // layer-1 output, fp16 (halves DRAM stream)
__device__ float g_pool2[Mn * 64];       // masked max over P of raw layer-2 output
__device__ unsigned char g_m8[Rn];
__device__ unsigned char g_valid[Mn];
__device__ float g_sum[3 * 64];
__device__ float g_sq[3 * 64];
__device__ int   g_cnt;
__device__ int   g_mode;   // 0=u8 bool, 1=int32, 2=float32

// packed-pair FMA: acc(f32x2) += {a,a} * w(f32x2)
__device__ __forceinline__ void fma2(float2 &acc, float a, float2 w) {
    float2 a2 = make_float2(a, a);
    asm("fma.rn.f32x2 %0, %1, %2, %0;"
        : "+l"(reinterpret_cast<unsigned long long &>(acc))
        : "l"(reinterpret_cast<unsigned long long &>(a2)),
          "l"(reinterpret_cast<unsigned long long &>(w)));
}

// ---------------- K0: zero accumulators + detect mask dtype ----------------
__global__ void k_init(const unsigned char *__restrict__ mraw) {
    int t = threadIdx.x;
    if (t < 192) { g_sum[t] = 0.f; g_sq[t] = 0.f; }
    if (t == 0) g_cnt = 0;
    __shared__ int fNB, fMis;
    if (t == 0) { fNB = 0; fMis = 0; }
    __syncthreads();
    for (int i = t; i < 1024; i += 256) {
        uchar4 v = reinterpret_cast<const uchar4 *>(mraw)[i];
        if ((v.x > 1) | (v.y > 1) | (v.z > 1) | (v.w > 1)) atomicOr(&fNB, 1);
        if ((v.y != 0) | (v.z != 0) | (v.w != 0)) atomicOr(&fMis, 1);
    }
    __syncthreads();
    if (t == 0) g_mode = fNB ? 2 : (fMis ? 0 : 1);
}

// ---------------- K1: mask pack + pre GEMM (C=9 -> H=64) + BN0 stats (scalar; measured 67us) ----------------
__global__ void __launch_bounds__(256) k_pre(const float *__restrict__ x,
                                             const float *__restrict__ Wp,
                                             const void *__restrict__ mraw) {
    __shared__ float xs[128 * 9];
    __shared__ float wp[576];
    __shared__ float msx[128];
    __shared__ float red[512];
    __shared__ int cw[4];
    int t = threadIdx.x;
    int r0 = blockIdx.x * 128;

    int bit = 0;
    if (t < 128) {
        int r = r0 + t;
        int mode = g_mode;
        if (mode == 0)      bit = reinterpret_cast<const unsigned char *>(mraw)[r] != 0;
        else if (mode == 1) bit = reinterpret_cast<const int *>(mraw)[r] != 0;
        else                bit = reinterpret_cast<const float *>(mraw)[r] != 0.f;
        g_m8[r] = (unsigned char)bit;
        msx[t] = (float)bit;
    }
    unsigned bal = __ballot_sync(0xffffffffu, bit);
    if (t < 128 && (t & 31) == 0) {
        g_valid[blockIdx.x * 4 + (t >> 5)] = bal ? 1 : 0;
        cw[t >> 5] = __popc(bal);
    }
    for (int i = t; i < 1152; i += 256) xs[i] = x[(size_t)r0 * 9 + i];
    for (int i = t; i < 576; i += 256) wp[i] = Wp[i];
    __syncthreads();
    if (t == 0) atomicAdd(&g_cnt, cw[0] + cw[1] + cw[2] + cw[3]);

    int j = t & 63, g = t >> 6;
    float s = 0.f, ss = 0.f;
    for (int lr = g * 32; lr < g * 32 + 32; lr++) {
        float h = 0.f;
#pragma unroll
        for (int c = 0; c < 9; c++) h = fmaf(xs[lr * 9 + c], wp[j * 9 + c], h);
        float m = msx[lr];
        s = fmaf(m, h, s);
        ss = fmaf(m * h, h, ss);
    }
    red[j * 4 + g] = s;
    red[256 + j * 4 + g] = ss;
    __syncthreads();
    if (t < 64) {
        float S  = red[t * 4] + red[t * 4 + 1] + red[t * 4 + 2] + red[t * 4 + 3];
        float SS = red[256 + t * 4] + red[256 + t * 4 + 1] + red[256 + t * 4 + 2] + red[256 + t * 4 + 3];
        atomicAdd(&g_sum[t], S);
        atomicAdd(&g_sq[t], SS);
    }
}

// ---------------- K2: layer1 (R11 form + inline fin0; h1 stored fp16) ----------------
__global__ void __launch_bounds__(256) k_mlp1(const float *__restrict__ x,
                                              const float *__restrict__ Wp,
                                              const float *__restrict__ gpre,
                                              const float *__restrict__ bpre,
                                              const float *__restrict__ W) {
    extern __shared__ float sm[];
    float *As = sm;                  // [128][68] = 8704
    float *Wa = sm + 8704;           // [64][68] = 4352 (aliased by xs/wpT in stage0)
    float *Wb = Wa + 4352;           // [64][68] = 4352
    float *pooledS = Wb + 4352;      // 256
    float *pcS = pooledS + 256;      // 256
    float *ms = pcS + 256;           // 128
    float *aS = ms + 128;            // 64
    float *bS = aS + 64;             // 64
    float *xs = Wa;                  // 1536 (alias)
    float *wpT = Wa + 1536;          // 576  (alias)

    int t = threadIdx.x;
    int r0 = blockIdx.x * 128;
    int p = t & 31;
    int h0 = (t >> 5) << 3;

    if (t < 128) ms[t] = (float)g_m8[r0 + t];
    if (t < 64) {   // inline fin0 from g_sum/g_sq
        float cnt = (float)g_cnt;
        float mean = g_sum[t] / cnt;
        float var = fmaxf(g_sq[t] / cnt - mean * mean, 0.f);
        float a = gpre[t] * rsqrtf(var + 1e-5f);
        aS[t] = a;
        bS[t] = bpre[t] - mean * a;
    }
    for (int idx = t; idx < 1152; idx += 256) {
        int row = idx / 9, c = idx - row * 9;
        xs[row * 12 + c] = x[(size_t)r0 * 9 + idx];
    }
    for (int idx = t; idx < 576; idx += 256) {
        int h = idx / 9, c = idx - h * 9;
        wpT[c * 64 + h] = Wp[idx];
    }
    __syncthreads();

    // recompute pre-layer into registers (vectorized), then BN0+ReLU+mask -> As
    {
        float2 acc[4][4];
#pragma unroll
        for (int q = 0; q < 4; q++)
#pragma unroll
            for (int j = 0; j < 4; j++) acc[q][j] = make_float2(0.f, 0.f);
#pragma unroll
        for (int qp = 0; qp < 2; qp++) {
            float4 ar[2][3];
#pragma unroll
            for (int s = 0; s < 2; s++) {
                int row = (qp * 2 + s) * 32 + p;
#pragma unroll
                for (int j = 0; j < 3; j++)
                    ar[s][j] = *reinterpret_cast<const float4 *>(&xs[row * 12 + 4 * j]);
            }
#pragma unroll
            for (int c = 0; c < 9; c++) {
                float4 wlo = *reinterpret_cast<const float4 *>(&wpT[c * 64 + h0]);
                float4 whi = *reinterpret_cast<const float4 *>(&wpT[c * 64 + h0 + 4]);
                float2 w0 = make_float2(wlo.x, wlo.y);
                float2 w1 = make_float2(wlo.z, wlo.w);
                float2 w2 = make_float2(whi.x, whi.y);
                float2 w3 = make_float2(whi.z, whi.w);
#pragma unroll
                for (int s = 0; s < 2; s++) {
                    float a = reinterpret_cast<const float *>(&ar[s][0])[c];
                    fma2(acc[qp * 2 + s][0], a, w0);
                    fma2(acc[qp * 2 + s][1], a, w1);
                    fma2(acc[qp * 2 + s][2], a, w2);
                    fma2(acc[qp * 2 + s][3], a, w3);
                }
            }
        }
        float av[8], bv[8];
#pragma unroll
        for (int i = 0; i < 8; i++) { av[i] = aS[h0 + i]; bv[i] = bS[h0 + i]; }
#pragma unroll
        for (int q = 0; q < 4; q++) {
            int row = q * 32 + p;
            float m = ms[row];
            float v[8];
#pragma unroll
            for (int i = 0; i < 8; i++) {
                float h = (i & 1) ? acc[q][i >> 1].y : acc[q][i >> 1].x;
                v[i] = fmaxf(fmaf(h, av[i], bv[i]), 0.f) * m;
            }
            *reinterpret_cast<float4 *>(&As[row * 68 + h0]) = make_float4(v[0], v[1], v[2], v[3]);
            *reinterpret_cast<float4 *>(&As[row * 68 + h0 + 4]) = make_float4(v[4], v[5], v[6], v[7]);
        }
    }
    __syncthreads();

    // load W1 transposed (coalesced gmem; one-shot STS conflicts absorbed)
    for (int idx = t; idx < 8192; idx += 256) {
        float v = W[idx];
        int h = idx >> 7, k2 = idx & 127;
        if (k2 < 64) Wa[k2 * 68 + h] = v;
        else Wb[(k2 - 64) * 68 + h] = v;
    }
    __syncthreads();

    // maxpool over P (values >=0; invalid rows exact zeros)
    {
        int q = t >> 6, k = t & 63;
        float mx = 0.f;
        for (int pp = 0; pp < 32; pp++) mx = fmaxf(mx, As[(q * 32 + pp) * 68 + k]);
        pooledS[q * 64 + k] = mx;
    }
    __syncthreads();
    // pooled contribution: pc[q][h] = sum_k pooled[q][k] * W[h][64+k]
    {
        int q = t >> 6, h = t & 63;
        float acc = 0.f;
        for (int k = 0; k < 64; k++) acc = fmaf(pooledS[q * 64 + k], Wb[k * 68 + h], acc);
        pcS[q * 64 + h] = acc;
    }
    __syncthreads();

    // GEMM: per thread -> 4 polylines x 8 channels
    float2 acc[4][4];
#pragma unroll
    for (int q = 0; q < 4; q++)
#pragma unroll
        for (int j = 0; j < 4; j++) acc[q][j] = make_float2(0.f, 0.f);

    for (int k = 0; k < 64; k += 4) {
        float av[4][4];
#pragma unroll
        for (int q = 0; q < 4; q++) {
            float4 tmp = *reinterpret_cast<const float4 *>(&As[(q * 32 + p) * 68 + k]);
            av[q][0] = tmp.x; av[q][1] = tmp.y; av[q][2] = tmp.z; av[q][3] = tmp.w;
        }
#pragma unroll
        for (int kk = 0; kk < 4; kk++) {
            const float *wr = &Wa[(k + kk) * 68 + h0];
            float4 wlo = *reinterpret_cast<const float4 *>(wr);
            float4 whi = *reinterpret_cast<const float4 *>(wr + 4);
            float2 w0 = make_float2(wlo.x, wlo.y);
            float2 w1 = make_float2(wlo.z, wlo.w);
            float2 w2 = make_float2(whi.x, whi.y);
            float2 w3 = make_float2(whi.z, whi.w);
#pragma unroll
            for (int q = 0; q < 4; q++) {
                float a = av[q][kk];
                fma2(acc[q][0], a, w0);
                fma2(acc[q][1], a, w1);
                fma2(acc[q][2], a, w2);
                fma2(acc[q][3], a, w3);
            }
        }
    }

    // epilogue: +pc, BN1 stats from fp32 values (exact), store h1 as fp16
    float vfin[4][8];
#pragma unroll
    for (int q = 0; q < 4; q++) {
#pragma unroll
        for (int j = 0; j < 4; j++) {
            vfin[q][2 * j]     = acc[q][j].x + pcS[q * 64 + h0 + 2 * j];
            vfin[q][2 * j + 1] = acc[q][j].y + pcS[q * 64 + h0 + 2 * j + 1];
        }
        size_t base = ((size_t)(r0 + q * 32 + p)) * 64 + h0;
        union { uint4 u; __half2 h[4]; } pk;
#pragma unroll
        for (int j = 0; j < 4; j++)
            pk.h[j] = __floats2half2_rn(vfin[q][2 * j], vfin[q][2 * j + 1]);
        *reinterpret_cast<uint4 *>(&g_h1[base]) = pk.u;
    }
    float mq[4];
#pragma unroll
    for (int q = 0; q < 4; q++) mq[q] = ms[q * 32 + p];
#pragma unroll
    for (int i = 0; i < 8; i++) {
        float s = 0.f, ss = 0.f;
#pragma unroll
        for (int q = 0; q < 4; q++) {
            float v = vfin[q][i];
            s = fmaf(mq[q], v, s);
            ss = fmaf(mq[q] * v, v, ss);
        }
#pragma unroll
        for (int off = 16; off > 0; off >>= 1) {
            s += __shfl_xor_sync(0xffffffffu, s, off);
            ss += __shfl_xor_sync(0xffffffffu, ss, off);
        }
        if (p == 0) {
            atomicAdd(&g_sum[64 + h0 + i], s);
            atomicAdd(&g_sq[64 + h0 + i], ss);
        }
    }
}

// ---------------- K3 (PROFILED @ idx 3): layer2 (R11 292us form; fp16 h1 read) ----------------
__global__ void __launch_bounds__(256) k_mlp2(const float *__restrict__ g1v,
                                              const float *__restrict__ b1v,
                                              const float *__restrict__ W) {
    extern __shared__ float sm[];
    float *As = sm;                  // [128][68] = 8704
    float *Wa = sm + 8704;           // [64][64]  = 4096
    float *ms = sm + 12800;          // 128
    float *aS = sm + 12928;          // 64
    float *bS = sm + 12992;          // 64  -> 13056 floats = 52224 B

    int t = threadIdx.x;
    int r0 = blockIdx.x * 128;
    int p = t & 31;
    int h0 = (t >> 5) << 3;
    int grp = p >> 3, lp = p & 7;

    if (t < 128) ms[t] = (float)g_m8[r0 + t];
    if (t < 64) {   // inline fin1
        float cnt = (float)g_cnt;
        float mean = g_sum[64 + t] / cnt;
        float var = fmaxf(g_sq[64 + t] / cnt - mean * mean, 0.f);
        float a = g1v[t] * rsqrtf(var + 1e-5f);
        aS[t] = a;
        bS[t] = b1v[t] - mean * a;
    }
    // W2 transpose: coalesced gmem (one-shot STS conflicts absorbed under MLP)
    for (int idx = t; idx < 4096; idx += 256) {
        int h = idx >> 6, k2 = idx & 63;
        Wa[k2 * 64 + h] = W[h * 64 + k2];
    }
    __syncthreads();

    // load h1 (fp16, 8 halves = 16B per access), BN1+ReLU+mask -> As (fp32)
    const uint4 *hin = reinterpret_cast<const uint4 *>(g_h1 + (size_t)r0 * 64);
    for (int i8 = t; i8 < 1024; i8 += 256) {
        union { uint4 u; __half2 h[4]; } pk;
        pk.u = hin[i8];
        int row = i8 >> 3;
        int kq = (i8 & 7) << 3;
        float m = ms[row];
        float v[8];
#pragma unroll
        for (int j = 0; j < 4; j++) {
            float2 f = __half22float2(pk.h[j]);
            v[2 * j]     = fmaxf(fmaf(f.x, aS[kq + 2 * j],     bS[kq + 2 * j]),     0.f) * m;
            v[2 * j + 1] = fmaxf(fmaf(f.y, aS[kq + 2 * j + 1], bS[kq + 2 * j + 1]), 0.f) * m;
        }
        *reinterpret_cast<float4 *>(&As[row * 68 + kq])     = make_float4(v[0], v[1], v[2], v[3]);
        *reinterpret_cast<float4 *>(&As[row * 68 + kq + 4]) = make_float4(v[4], v[5], v[6], v[7]);
    }
    __syncthreads();

    int rowB[4];
#pragma unroll
    for (int q = 0; q < 4; q++) rowB[q] = grp * 32 + 8 * q + lp;

    float2 acc[4][4];
#pragma unroll
    for (int q = 0; q < 4; q++)
#pragma unroll
        for (int j = 0; j < 4; j++) acc[q][j] = make_float2(0.f, 0.f);

#pragma unroll
    for (int k = 0; k < 64; k += 4) {
        float av[4][4];
#pragma unroll
        for (int q = 0; q < 4; q++) {
            float4 tmp = *reinterpret_cast<const float4 *>(&As[rowB[q] * 68 + k]);
            av[q][0] = tmp.x; av[q][1] = tmp.y; av[q][2] = tmp.z; av[q][3] = tmp.w;
        }
#pragma unroll
        for (int kk = 0; kk < 4; kk++) {
            float4 wlo = *reinterpret_cast<const float4 *>(&Wa[(k + kk) * 64 + h0]);
            float4 whi = *reinterpret_cast<const float4 *>(&Wa[(k + kk) * 64 + h0 + 4]);
            float2 w0 = make_float2(wlo.x, wlo.y);
            float2 w1 = make_float2(wlo.z, wlo.w);
            float2 w2 = make_float2(whi.x, whi.y);
            float2 w3 = make_float2(whi.z, whi.w);
#pragma unroll
            for (int q = 0; q < 4; q++) {
                float a = av[q][kk];
                fma2(acc[q][0], a, w0);
                fma2(acc[q][1], a, w1);
                fma2(acc[q][2], a, w2);
                fma2(acc[q][3], a, w3);
            }
        }
    }

    // epilogue: BN2 stats + masked max over the polyline (in-thread + 3 shuffles)
    float mq[4];
#pragma unroll
    for (int q = 0; q < 4; q++) mq[q] = ms[rowB[q]];

    float mxv[8];
#pragma unroll
    for (int i = 0; i < 8; i++) mxv[i] = -3.4e38f;

#pragma unroll
    for (int i = 0; i < 8; i++) {
        float s = 0.f, ss = 0.f;
#pragma unroll
        for (int q = 0; q < 4; q++) {
            float v = (i & 1) ? acc[q][i >> 1].y : acc[q][i >> 1].x;
            s = fmaf(mq[q], v, s);
            ss = fmaf(mq[q] * v, v, ss);
            float cand = (mq[q] > 0.f) ? v : -3.4e38f;
            mxv[i] = fmaxf(mxv[i], cand);
        }
#pragma unroll
        for (int off = 16; off > 0; off >>= 1) {
            s += __shfl_xor_sync(0xffffffffu, s, off);
            ss += __shfl_xor_sync(0xffffffffu, ss, off);
        }
        if (p == 0) {
            atomicAdd(&g_sum[128 + h0 + i], s);
            atomicAdd(&g_sq[128 + h0 + i], ss);
        }
    }
#pragma unroll
    for (int i = 0; i < 8; i++) {
#pragma unroll
        for (int d = 1; d < 8; d <<= 1)
            mxv[i] = fmaxf(mxv[i], __shfl_xor_sync(0xffffffffu, mxv[i], d));
    }
    if (lp == 0) {
        size_t base = (size_t)(blockIdx.x * 4 + grp) * 64 + h0;
        *reinterpret_cast<float4 *>(&g_pool2[base]) = make_float4(mxv[0], mxv[1], mxv[2], mxv[3]);
        *reinterpret_cast<float4 *>(&g_pool2[base + 4]) = make_float4(mxv[4], mxv[5], mxv[6], mxv[7]);
    }
}

// ---------------- K4: blocked out-MLP (R11 exact) ----------------
__global__ void __launch_bounds__(256) k_out(const float *__restrict__ g2,
                                             const float *__restrict__ b2v,
                                             const float *__restrict__ Wo1,
                                             const float *__restrict__ bo1,
                                             const float *__restrict__ Wo2,
                                             const float *__restrict__ bo2,
                                             float *__restrict__ out) {
    extern __shared__ float sm[];
    float *poolS = sm;            // [128][68] = 8704
    float *y1S = sm + 8704;       // [128][68] = 8704
    float *W1T = sm + 17408;      // [64][64]  = 4096
    float *W2T = sm + 21504;      // [64][128] = 8192
    float *bo1S = sm + 29696;     // 64
    float *bo2S = sm + 29760;     // 128
    float *aS = sm + 29888;       // 64
    float *bS = sm + 29952;       // 64   -> 30016 floats = 120064 B

    int t = threadIdx.x;
    int p = t & 31;
    int h0 = (t >> 5) << 3;

    if (t < 64) {
        float cnt = (float)g_cnt;
        float mean = g_sum[128 + t] / cnt;
        float var = fmaxf(g_sq[128 + t] / cnt - mean * mean, 0.f);
        float a = g2[t] * rsqrtf(var + 1e-5f);
        aS[t] = a;
        bS[t] = b2v[t] - mean * a;
        bo1S[t] = bo1[t];
    }
    if (t < 128) bo2S[t] = bo2[t];
    for (int idx = t; idx < 4096; idx += 256) {
        int h = idx >> 6, k = idx & 63;
        W1T[k * 64 + h] = Wo1[idx];
    }
    for (int idx = t; idx < 8192; idx += 256) {
        int o = idx >> 6, k = idx & 63;
        W2T[k * 128 + o] = Wo2[idx];
    }
    __syncthreads();

    for (int tile = 0; tile < 2; tile++) {
        int bn0 = (blockIdx.x * 2 + tile) * 128;
        const float4 *p4 = reinterpret_cast<const float4 *>(g_pool2 + (size_t)bn0 * 64);
        for (int i4 = t; i4 < 2048; i4 += 256) {
            float4 v = p4[i4];
            int row = i4 >> 4, c = (i4 & 15) << 2;
            v.x = fmaxf(fmaf(v.x, aS[c + 0], bS[c + 0]), 0.f);
            v.y = fmaxf(fmaf(v.y, aS[c + 1], bS[c + 1]), 0.f);
            v.z = fmaxf(fmaf(v.z, aS[c + 2], bS[c + 2]), 0.f);
            v.w = fmaxf(fmaf(v.w, aS[c + 3], bS[c + 3]), 0.f);
            *reinterpret_cast<float4 *>(&poolS[row * 68 + c]) = v;
        }
        __syncthreads();

        // y1 = relu(pool @ Wo1^T + bo1)
        {
            float2 acc[4][4];
#pragma unroll
            for (int q = 0; q < 4; q++)
#pragma unroll
                for (int j = 0; j < 4; j++) acc[q][j] = make_float2(0.f, 0.f);
#pragma unroll
            for (int k = 0; k < 64; k += 4) {
                float av[4][4];
#pragma unroll
                for (int q = 0; q < 4; q++) {
                    float4 tmp = *reinterpret_cast<const float4 *>(&poolS[(q * 32 + p) * 68 + k]);
                    av[q][0] = tmp.x; av[q][1] = tmp.y; av[q][2] = tmp.z; av[q][3] = tmp.w;
                }
#pragma unroll
                for (int kk = 0; kk < 4; kk++) {
                    float4 wlo = *reinterpret_cast<const float4 *>(&W1T[(k + kk) * 64 + h0]);
                    float4 whi = *reinterpret_cast<const float4 *>(&W1T[(k + kk) * 64 + h0 + 4]);
                    float2 w0 = make_float2(wlo.x, wlo.y);
                    float2 w1 = make_float2(wlo.z, wlo.w);
                    float2 w2 = make_float2(whi.x, whi.y);
                    float2 w3 = make_float2(whi.z, whi.w);
#pragma unroll
                    for (int q = 0; q < 4; q++) {
                        float a = av[q][kk];
                        fma2(acc[q][0], a, w0);
                        fma2(acc[q][1], a, w1);
                        fma2(acc[q][2], a, w2);
                        fma2(acc[q][3], a, w3);
                    }
                }
            }
#pragma unroll
            for (int q = 0; q < 4; q++) {
                int row = q * 32 + p;
                float v[8];
#pragma unroll
                for (int i = 0; i < 8; i++) {
                    float hv = (i & 1) ? acc[q][i >> 1].y : acc[q][i >> 1].x;
                    v[i] = fmaxf(hv + bo1S[h0 + i], 0.f);
                }
                *reinterpret_cast<float4 *>(&y1S[row * 68 + h0]) = make_float4(v[0], v[1], v[2], v[3]);
                *reinterpret_cast<float4 *>(&y1S[row * 68 + h0 + 4]) = make_float4(v[4], v[5], v[6], v[7]);
            }
        }
        __syncthreads();

        // y2 = (y1 @ Wo2^T + bo2) * valid
#pragma unroll
        for (int half = 0; half < 2; half++) {
            int o0 = h0 + 64 * half;
            float2 acc[4][4];
#pragma unroll
            for (int q = 0; q < 4; q++)
#pragma unroll
                for (int j = 0; j < 4; j++) acc[q][j] = make_float2(0.f, 0.f);
#pragma unroll
            for (int k = 0; k < 64; k += 4) {
                float av[4][4];
#pragma unroll
                for (int q = 0; q < 4; q++) {
                    float4 tmp = *reinterpret_cast<const float4 *>(&y1S[(q * 32 + p) * 68 + k]);
                    av[q][0] = tmp.x; av[q][1] = tmp.y; av[q][2] = tmp.z; av[q][3] = tmp.w;
                }
#pragma unroll
                for (int kk = 0; kk < 4; kk++) {
                    float4 wlo = *reinterpret_cast<const float4 *>(&W2T[(k + kk) * 128 + o0]);
                    float4 whi = *reinterpret_cast<const float4 *>(&W2T[(k + kk) * 128 + o0 + 4]);
                    float2 w0 = make_float2(wlo.x, wlo.y);
                    float2 w1 = make_float2(wlo.z, wlo.w);
                    float2 w2 = make_float2(whi.x, whi.y);
                    float2 w3 = make_float2(whi.z, whi.w);
#pragma unroll
                    for (int q = 0; q < 4; q++) {
                        float a = av[q][kk];
                        fma2(acc[q][0], a, w0);
                        fma2(acc[q][1], a, w1);
                        fma2(acc[q][2], a, w2);
                        fma2(acc[q][3], a, w3);
                    }
                }
            }
#pragma unroll
            for (int q = 0; q < 4; q++) {
                int row = q * 32 + p;
                float vf = g_valid[bn0 + row] ? 1.f : 0.f;
                float v[8];
#pragma unroll
                for (int i = 0; i < 8; i++) {
                    float hv = (i & 1) ? acc[q][i >> 1].y : acc[q][i >> 1].x;
                    v[i] = (hv + bo2S[o0 + i]) * vf;
                }
                size_t base = (size_t)(bn0 + row) * 128 + o0;
                *reinterpret_cast<float4 *>(&out[base]) = make_float4(v[0], v[1], v[2], v[3]);
                *reinterpret_cast<float4 *>(&out[base + 4]) = make_float4(v[4], v[5], v[6], v[7]);
            }
        }
        __syncthreads();
    }
}

// ---------------- launcher ----------------
extern "C" void kernel_launch(void *const *d_in, const int *in_sizes, int n_in,
                              void *d_out, int out_size) {
    const float *poly = (const float *)d_in[0];
    const void *mask = d_in[1];
    const float *Wpre = (const float *)d_in[2];
    const float *gpre = (const float *)d_in[3];
    const float *bpre = (const float *)d_in[4];
    const float *W1 = (const float *)d_in[5];
    const float *g1 = (const float *)d_in[6];
    const float *b1 = (const float *)d_in[7];
    const float *W2 = (const float *)d_in[8];
    const float *g2 = (const float *)d_in[9];
    const float *b2 = (const float *)d_in[10];
    const float *Wo1 = (const float *)d_in[11];
    const float *bo1 = (const float *)d_in[12];
    const float *Wo2 = (const float *)d_in[13];
    const float *bo2 = (const float *)d_in[14];
    float *out = (float *)d_out;

    cudaFuncSetAttribute(k_mlp1, cudaFuncAttributeMaxDynamicSharedMemorySize, 72704);
    cudaFuncSetAttribute(k_mlp2, cudaFuncAttributeMaxDynamicSharedMemorySize, 52224);
    cudaFuncSetAttribute(k_out,  cudaFuncAttributeMaxDynamicSharedMemorySize, 120064);

    k_init<<<1, 256>>>((const unsigned char *)mask);                 // idx 0
    k_pre<<<6144, 256>>>(poly, Wpre, mask);                          // idx 1
    k_mlp1<<<6144, 256, 72704>>>(poly, Wpre, gpre, bpre, W1);        // idx 2
    k_mlp2<<<6144, 256, 52224>>>(g1, b1, W2);                        // idx 3  <- profiled
    k_out<<<96, 256, 120064>>>(g2, b2, Wo1, bo1, Wo2, bo2, out);     // idx 4
}

// round 16
// speedup vs baseline: 1.4693x; 1.3794x over previous
#include <cuda_runtime.h>
#include <cuda_fp16.h>
#include <cstdint>

#define Rn 786432      // B*N*P
#define Mn 24576       // B*N

// ---------------- scratch (static device globals; no allocation) ----------------
__device__ __half g_h1[Rn * 64];         // layer-1 output, fp16
__device__ float g_pool2[Mn * 64];       // masked max over P of raw layer-2 output
__device__ unsigned char g_m8[Rn];
__device__ unsigned char g_valid[Mn];
__device__ float g_sum[3 * 64];
__device__ float g_sq[3 * 64];
__device__ int   g_cnt;
__device__ int   g_mode;   // 0=u8 bool, 1=int32, 2=float32

// packed-pair FMA: acc(f32x2) += {a,a} * w(f32x2)
__device__ __forceinline__ void fma2(float2 &acc, float a, float2 w) {
    float2 a2 = make_float2(a, a);
    asm("fma.rn.f32x2 %0, %1, %2, %0;"
        : "+l"(reinterpret_cast<unsigned long long &>(acc))
        : "l"(reinterpret_cast<unsigned long long &>(a2)),
          "l"(reinterpret_cast<unsigned long long &>(w)));
}

// mma.sync m16n8k16 fp16 in, fp32 accum
__device__ __forceinline__ void mma16816(float &c0, float &c1, float &c2, float &c3,
                                         unsigned a0, unsigned a1, unsigned a2, unsigned a3,
                                         unsigned b0, unsigned b1) {
    asm volatile(
        "mma.sync.aligned.m16n8k16.row.col.f32.f16.f16.f32 "
        "{%0,%1,%2,%3}, {%4,%5,%6,%7}, {%8,%9}, {%0,%1,%2,%3};"
        : "+f"(c0), "+f"(c1), "+f"(c2), "+f"(c3)
        : "r"(a0), "r"(a1), "r"(a2), "r"(a3), "r"(b0), "r"(b1));
}

// ---------------- K0: zero accumulators + detect mask dtype ----------------
__global__ void k_init(const unsigned char *__restrict__ mraw) {
    int t = threadIdx.x;
    if (t < 192) { g_sum[t] = 0.f; g_sq[t] = 0.f; }
    if (t == 0) g_cnt = 0;
    __shared__ int fNB, fMis;
    if (t == 0) { fNB = 0; fMis = 0; }
    __syncthreads();
    for (int i = t; i < 1024; i += 256) {
        uchar4 v = reinterpret_cast<const uchar4 *>(mraw)[i];
        if ((v.x > 1) | (v.y > 1) | (v.z > 1) | (v.w > 1)) atomicOr(&fNB, 1);
        if ((v.y != 0) | (v.z != 0) | (v.w != 0)) atomicOr(&fMis, 1);
    }
    __syncthreads();
    if (t == 0) g_mode = fNB ? 2 : (fMis ? 0 : 1);
}

// ---------------- K1: mask pack + pre GEMM (C=9 -> H=64) + BN0 stats ----------------
__global__ void __launch_bounds__(256) k_pre(const float *__restrict__ x,
                                             const float *__restrict__ Wp,
                                             const void *__restrict__ mraw) {
    __shared__ float xs[128 * 9];
    __shared__ float wp[576];
    __shared__ float msx[128];
    __shared__ float red[512];
    __shared__ int cw[4];
    int t = threadIdx.x;
    int r0 = blockIdx.x * 128;

    int bit = 0;
    if (t < 128) {
        int r = r0 + t;
        int mode = g_mode;
        if (mode == 0)      bit = reinterpret_cast<const unsigned char *>(mraw)[r] != 0;
        else if (mode == 1) bit = reinterpret_cast<const int *>(mraw)[r] != 0;
        else                bit = reinterpret_cast<const float *>(mraw)[r] != 0.f;
        g_m8[r] = (unsigned char)bit;
        msx[t] = (float)bit;
    }
    unsigned bal = __ballot_sync(0xffffffffu, bit);
    if (t < 128 && (t & 31) == 0) {
        g_valid[blockIdx.x * 4 + (t >> 5)] = bal ? 1 : 0;
        cw[t >> 5] = __popc(bal);
    }
    for (int i = t; i < 1152; i += 256) xs[i] = x[(size_t)r0 * 9 + i];
    for (int i = t; i < 576; i += 256) wp[i] = Wp[i];
    __syncthreads();
    if (t == 0) atomicAdd(&g_cnt, cw[0] + cw[1] + cw[2] + cw[3]);

    int j = t & 63, g = t >> 6;
    float s = 0.f, ss = 0.f;
    for (int lr = g * 32; lr < g * 32 + 32; lr++) {
        float h = 0.f;
#pragma unroll
        for (int c = 0; c < 9; c++) h = fmaf(xs[lr * 9 + c], wp[j * 9 + c], h);
        float m = msx[lr];
        s = fmaf(m, h, s);
        ss = fmaf(m * h, h, ss);
    }
    red[j * 4 + g] = s;
    red[256 + j * 4 + g] = ss;
    __syncthreads();
    if (t < 64) {
        float S  = red[t * 4] + red[t * 4 + 1] + red[t * 4 + 2] + red[t * 4 + 3];
        float SS = red[256 + t * 4] + red[256 + t * 4 + 1] + red[256 + t * 4 + 2] + red[256 + t * 4 + 3];
        atomicAdd(&g_sum[t], S);
        atomicAdd(&g_sq[t], SS);
    }
}

// ---------------- K2: layer1 (R15 exact; fp16 h1 store) ----------------
__global__ void __launch_bounds__(256) k_mlp1(const float *__restrict__ x,
                                              const float *__restrict__ Wp,
                                              const float *__restrict__ gpre,
                                              const float *__restrict__ bpre,
                                              const float *__restrict__ W) {
    extern __shared__ float sm[];
    float *As = sm;                  // [128][68] = 8704
    float *Wa = sm + 8704;           // [64][68] = 4352 (aliased by xs/wpT in stage0)
    float *Wb = Wa + 4352;           // [64][68] = 4352
    float *pooledS = Wb + 4352;      // 256
    float *pcS = pooledS + 256;      // 256
    float *ms = pcS + 256;           // 128
    float *aS = ms + 128;            // 64
    float *bS = aS + 64;             // 64
    float *xs = Wa;                  // 1536 (alias)
    float *wpT = Wa + 1536;          // 576  (alias)

    int t = threadIdx.x;
    int r0 = blockIdx.x * 128;
    int p = t & 31;
    int h0 = (t >> 5) << 3;

    if (t < 128) ms[t] = (float)g_m8[r0 + t];
    if (t < 64) {
        float cnt = (float)g_cnt;
        float mean = g_sum[t] / cnt;
        float var = fmaxf(g_sq[t] / cnt - mean * mean, 0.f);
        float a = gpre[t] * rsqrtf(var + 1e-5f);
        aS[t] = a;
        bS[t] = bpre[t] - mean * a;
    }
    for (int idx = t; idx < 1152; idx += 256) {
        int row = idx / 9, c = idx - row * 9;
        xs[row * 12 + c] = x[(size_t)r0 * 9 + idx];
    }
    for (int idx = t; idx < 576; idx += 256) {
        int h = idx / 9, c = idx - h * 9;
        wpT[c * 64 + h] = Wp[idx];
    }
    __syncthreads();

    {
        float2 acc[4][4];
#pragma unroll
        for (int q = 0; q < 4; q++)
#pragma unroll
            for (int j = 0; j < 4; j++) acc[q][j] = make_float2(0.f, 0.f);
#pragma unroll
        for (int qp = 0; qp < 2; qp++) {
            float4 ar[2][3];
#pragma unroll
            for (int s = 0; s < 2; s++) {
                int row = (qp * 2 + s) * 32 + p;
#pragma unroll
                for (int j = 0; j < 3; j++)
                    ar[s][j] = *reinterpret_cast<const float4 *>(&xs[row * 12 + 4 * j]);
            }
#pragma unroll
            for (int c = 0; c < 9; c++) {
                float4 wlo = *reinterpret_cast<const float4 *>(&wpT[c * 64 + h0]);
                float4 whi = *reinterpret_cast<const float4 *>(&wpT[c * 64 + h0 + 4]);
                float2 w0 = make_float2(wlo.x, wlo.y);
                float2 w1 = make_float2(wlo.z, wlo.w);
                float2 w2 = make_float2(whi.x, whi.y);
                float2 w3 = make_float2(whi.z, whi.w);
#pragma unroll
                for (int s = 0; s < 2; s++) {
                    float a = reinterpret_cast<const float *>(&ar[s][0])[c];
                    fma2(acc[qp * 2 + s][0], a, w0);
                    fma2(acc[qp * 2 + s][1], a, w1);
                    fma2(acc[qp * 2 + s][2], a, w2);
                    fma2(acc[qp * 2 + s][3], a, w3);
                }
            }
        }
        float av[8], bv[8];
#pragma unroll
        for (int i = 0; i < 8; i++) { av[i] = aS[h0 + i]; bv[i] = bS[h0 + i]; }
#pragma unroll
        for (int q = 0; q < 4; q++) {
            int row = q * 32 + p;
            float m = ms[row];
            float v[8];
#pragma unroll
            for (int i = 0; i < 8; i++) {
                float h = (i & 1) ? acc[q][i >> 1].y : acc[q][i >> 1].x;
                v[i] = fmaxf(fmaf(h, av[i], bv[i]), 0.f) * m;
            }
            *reinterpret_cast<float4 *>(&As[row * 68 + h0]) = make_float4(v[0], v[1], v[2], v[3]);
            *reinterpret_cast<float4 *>(&As[row * 68 + h0 + 4]) = make_float4(v[4], v[5], v[6], v[7]);
        }
    }
    __syncthreads();

    for (int idx = t; idx < 8192; idx += 256) {
        float v = W[idx];
        int h = idx >> 7, k2 = idx & 127;
        if (k2 < 64) Wa[k2 * 68 + h] = v;
        else Wb[(k2 - 64) * 68 + h] = v;
    }
    __syncthreads();

    {
        int q = t >> 6, k = t & 63;
        float mx = 0.f;
        for (int pp = 0; pp < 32; pp++) mx = fmaxf(mx, As[(q * 32 + pp) * 68 + k]);
        pooledS[q * 64 + k] = mx;
    }
    __syncthreads();
    {
        int q = t >> 6, h = t & 63;
        float acc = 0.f;
        for (int k = 0; k < 64; k++) acc = fmaf(pooledS[q * 64 + k], Wb[k * 68 + h], acc);
        pcS[q * 64 + h] = acc;
    }
    __syncthreads();

    float2 acc[4][4];
#pragma unroll
    for (int q = 0; q < 4; q++)
#pragma unroll
        for (int j = 0; j < 4; j++) acc[q][j] = make_float2(0.f, 0.f);

    for (int k = 0; k < 64; k += 4) {
        float av[4][4];
#pragma unroll
        for (int q = 0; q < 4; q++) {
            float4 tmp = *reinterpret_cast<const float4 *>(&As[(q * 32 + p) * 68 + k]);
            av[q][0] = tmp.x; av[q][1] = tmp.y; av[q][2] = tmp.z; av[q][3] = tmp.w;
        }
#pragma unroll
        for (int kk = 0; kk < 4; kk++) {
            const float *wr = &Wa[(k + kk) * 68 + h0];
            float4 wlo = *reinterpret_cast<const float4 *>(wr);
            float4 whi = *reinterpret_cast<const float4 *>(wr + 4);
            float2 w0 = make_float2(wlo.x, wlo.y);
            float2 w1 = make_float2(wlo.z, wlo.w);
            float2 w2 = make_float2(whi.x, whi.y);
            float2 w3 = make_float2(whi.z, whi.w);
#pragma unroll
            for (int q = 0; q < 4; q++) {
                float a = av[q][kk];
                fma2(acc[q][0], a, w0);
                fma2(acc[q][1], a, w1);
                fma2(acc[q][2], a, w2);
                fma2(acc[q][3], a, w3);
            }
        }
    }

    float vfin[4][8];
#pragma unroll
    for (int q = 0; q < 4; q++) {
#pragma unroll
        for (int j = 0; j < 4; j++) {
            vfin[q][2 * j]     = acc[q][j].x + pcS[q * 64 + h0 + 2 * j];
            vfin[q][2 * j + 1] = acc[q][j].y + pcS[q * 64 + h0 + 2 * j + 1];
        }
        size_t base = ((size_t)(r0 + q * 32 + p)) * 64 + h0;
        union { uint4 u; __half2 h[4]; } pk;
#pragma unroll
        for (int j = 0; j < 4; j++)
            pk.h[j] = __floats2half2_rn(vfin[q][2 * j], vfin[q][2 * j + 1]);
        *reinterpret_cast<uint4 *>(&g_h1[base]) = pk.u;
    }
    float mq[4];
#pragma unroll
    for (int q = 0; q < 4; q++) mq[q] = ms[q * 32 + p];
#pragma unroll
    for (int i = 0; i < 8; i++) {
        float s = 0.f, ss = 0.f;
#pragma unroll
        for (int q = 0; q < 4; q++) {
            float v = vfin[q][i];
            s = fmaf(mq[q], v, s);
            ss = fmaf(mq[q] * v, v, ss);
        }
#pragma unroll
        for (int off = 16; off > 0; off >>= 1) {
            s += __shfl_xor_sync(0xffffffffu, s, off);
            ss += __shfl_xor_sync(0xffffffffu, ss, off);
        }
        if (p == 0) {
            atomicAdd(&g_sum[64 + h0 + i], s);
            atomicAdd(&g_sq[64 + h0 + i], ss);
        }
    }
}

// ---------------- K3 (PROFILED @ idx 3): layer2 via mma.sync m16n8k16 fp16 ----------------
// smem: [0, 34816)B shared region: phase A = As16(128x72 half, 18432B) + Wh16(64x72 half, 9216B);
//       phase B (after mainloop) = V fp32 [128][68] (34816B) overwrites.
__global__ void __launch_bounds__(256) k_mlp2(const float *__restrict__ g1v,
                                              const float *__restrict__ b1v,
                                              const float *__restrict__ W) {
    extern __shared__ float sm[];
    float *V = sm;                                   // [128][68] fp32 (phase B)
    __half *As16 = reinterpret_cast<__half *>(sm);   // [128][72] (phase A)
    __half *Wh16 = As16 + 9216;                      // [64][72]  (phase A)
    float *ms = sm + 8704;                           // 128   (8704 floats = 34816 B)
    float *aS = sm + 8832;                           // 64
    float *bS = sm + 8896;                           // 64
    float *partS = sm + 8960;                        // 256
    float *partSS = sm + 9216;                       // 256  -> 9472 floats = 37888 B

    int t = threadIdx.x;
    int r0 = blockIdx.x * 128;
    int p = t & 31;
    int wid = t >> 5;
    int h0 = wid << 3;
    int g = p >> 2, tp = p & 3;

    if (t < 128) ms[t] = (float)g_m8[r0 + t];
    if (t < 64) {   // inline fin1
        float cnt = (float)g_cnt;
        float mean = g_sum[64 + t] / cnt;
        float var = fmaxf(g_sq[64 + t] / cnt - mean * mean, 0.f);
        float a = g1v[t] * rsqrtf(var + 1e-5f);
        aS[t] = a;
        bS[t] = b1v[t] - mean * a;
    }
    // stage W2 as fp16, layout Wh16[ch][k] (col-major B for mma), stride 72
    for (int idx = t; idx < 4096; idx += 256) {
        int h = idx >> 6, k2 = idx & 63;
        Wh16[h * 72 + k2] = __float2half_rn(W[idx]);
    }
    __syncthreads();

    // load h1 fp16, BN1+ReLU+mask in fp32, store fp16 -> As16 (stride 72)
    const uint4 *hin = reinterpret_cast<const uint4 *>(g_h1 + (size_t)r0 * 64);
    for (int i8 = t; i8 < 1024; i8 += 256) {
        union { uint4 u; __half2 h[4]; } pk, po;
        pk.u = hin[i8];
        int row = i8 >> 3;
        int kq = (i8 & 7) << 3;
        float m = ms[row];
#pragma unroll
        for (int j = 0; j < 4; j++) {
            float2 f = __half22float2(pk.h[j]);
            float v0 = fmaxf(fmaf(f.x, aS[kq + 2 * j],     bS[kq + 2 * j]),     0.f) * m;
            float v1 = fmaxf(fmaf(f.y, aS[kq + 2 * j + 1], bS[kq + 2 * j + 1]), 0.f) * m;
            po.h[j] = __floats2half2_rn(v0, v1);
        }
        *reinterpret_cast<uint4 *>(&As16[row * 72 + kq]) = po.u;
    }
    __syncthreads();

    // mainloop: warp covers 128 rows x 8 channels (h0..h0+7), K=64
    // B fragments preloaded: b[kt][0..1], kt = k-tile (16 k each)
    unsigned bfr[4][2];
#pragma unroll
    for (int kt = 0; kt < 4; kt++) {
        const __half *wb = &Wh16[(h0 + g) * 72 + kt * 16 + 2 * tp];
        bfr[kt][0] = *reinterpret_cast<const unsigned *>(wb);
        bfr[kt][1] = *reinterpret_cast<const unsigned *>(wb + 8);
    }
    float c[8][4];
#pragma unroll
    for (int mt = 0; mt < 8; mt++)
#pragma unroll
        for (int j = 0; j < 4; j++) c[mt][j] = 0.f;

#pragma unroll
    for (int kt = 0; kt < 4; kt++) {
#pragma unroll
        for (int mt = 0; mt < 8; mt++) {
            const __half *ab = &As16[(mt * 16 + g) * 72 + kt * 16 + 2 * tp];
            unsigned a0 = *reinterpret_cast<const unsigned *>(ab);
            unsigned a1 = *reinterpret_cast<const unsigned *>(ab + 8 * 72);
            unsigned a2 = *reinterpret_cast<const unsigned *>(ab + 8);
            unsigned a3 = *reinterpret_cast<const unsigned *>(ab + 8 * 72 + 8);
            mma16816(c[mt][0], c[mt][1], c[mt][2], c[mt][3],
                     a0, a1, a2, a3, bfr[kt][0], bfr[kt][1]);
        }
    }
    __syncthreads();   // all reads of As16/Wh16 done; V may overwrite

    // dump C fragments -> V fp32 [row][ch], stride 68
    // c0,c1: row = mt*16+g, cols h0+2tp, +1 ; c2,c3: row+8
#pragma unroll
    for (int mt = 0; mt < 8; mt++) {
        int row = mt * 16 + g;
        *reinterpret_cast<float2 *>(&V[row * 68 + h0 + 2 * tp]) = make_float2(c[mt][0], c[mt][1]);
        *reinterpret_cast<float2 *>(&V[(row + 8) * 68 + h0 + 2 * tp]) = make_float2(c[mt][2], c[mt][3]);
    }
    __syncthreads();

    // streaming pass: stats + per-polyline masked max
    {
        int ch = t & 63, qq = t >> 6;
        float s = 0.f, ss = 0.f, mx = -3.4e38f;
#pragma unroll 8
        for (int r = 0; r < 32; r++) {
            int row = qq * 32 + r;
            float v = V[row * 68 + ch];
            float m = ms[row];
            s = fmaf(m, v, s);
            ss = fmaf(m * v, v, ss);
            mx = fmaxf(mx, (m > 0.f) ? v : -3.4e38f);
        }
        g_pool2[(size_t)(blockIdx.x * 4 + qq) * 64 + ch] = mx;
        partS[qq * 64 + ch] = s;
        partSS[qq * 64 + ch] = ss;
    }
    __syncthreads();
    if (t < 64) {
        float S  = partS[t] + partS[64 + t] + partS[128 + t] + partS[192 + t];
        float SS = partSS[t] + partSS[64 + t] + partSS[128 + t] + partSS[192 + t];
        atomicAdd(&g_sum[128 + t], S);
        atomicAdd(&g_sq[128 + t], SS);
    }
}

// ---------------- K4: blocked out-MLP (R11 exact) ----------------
__global__ void __launch_bounds__(256) k_out(const float *__restrict__ g2,
                                             const float *__restrict__ b2v,
                                             const float *__restrict__ Wo1,
                                             const float *__restrict__ bo1,
                                             const float *__restrict__ Wo2,
                                             const float *__restrict__ bo2,
                                             float *__restrict__ out) {
    extern __shared__ float sm[];
    float *poolS = sm;            // [128][68] = 8704
    float *y1S = sm + 8704;       // [128][68] = 8704
    float *W1T = sm + 17408;      // [64][64]  = 4096
    float *W2T = sm + 21504;      // [64][128] = 8192
    float *bo1S = sm + 29696;     // 64
    float *bo2S = sm + 29760;     // 128
    float *aS = sm + 29888;       // 64
    float *bS = sm + 29952;       // 64   -> 30016 floats = 120064 B

    int t = threadIdx.x;
    int p = t & 31;
    int h0 = (t >> 5) << 3;

    if (t < 64) {
        float cnt = (float)g_cnt;
        float mean = g_sum[128 + t] / cnt;
        float var = fmaxf(g_sq[128 + t] / cnt - mean * mean, 0.f);
        float a = g2[t] * rsqrtf(var + 1e-5f);
        aS[t] = a;
        bS[t] = b2v[t] - mean * a;
        bo1S[t] = bo1[t];
    }
    if (t < 128) bo2S[t] = bo2[t];
    for (int idx = t; idx < 4096; idx += 256) {
        int h = idx >> 6, k = idx & 63;
        W1T[k * 64 + h] = Wo1[idx];
    }
    for (int idx = t; idx < 8192; idx += 256) {
        int o = idx >> 6, k = idx & 63;
        W2T[k * 128 + o] = Wo2[idx];
    }
    __syncthreads();

    for (int tile = 0; tile < 2; tile++) {
        int bn0 = (blockIdx.x * 2 + tile) * 128;
        const float4 *p4 = reinterpret_cast<const float4 *>(g_pool2 + (size_t)bn0 * 64);
        for (int i4 = t; i4 < 2048; i4 += 256) {
            float4 v = p4[i4];
            int row = i4 >> 4, c = (i4 & 15) << 2;
            v.x = fmaxf(fmaf(v.x, aS[c + 0], bS[c + 0]), 0.f);
            v.y = fmaxf(fmaf(v.y, aS[c + 1], bS[c + 1]), 0.f);
            v.z = fmaxf(fmaf(v.z, aS[c + 2], bS[c + 2]), 0.f);
            v.w = fmaxf(fmaf(v.w, aS[c + 3], bS[c + 3]), 0.f);
            *reinterpret_cast<float4 *>(&poolS[row * 68 + c]) = v;
        }
        __syncthreads();

        {
            float2 acc[4][4];
#pragma unroll
            for (int q = 0; q < 4; q++)
#pragma unroll
                for (int j = 0; j < 4; j++) acc[q][j] = make_float2(0.f, 0.f);
#pragma unroll
            for (int k = 0; k < 64; k += 4) {
                float av[4][4];
#pragma unroll
                for (int q = 0; q < 4; q++) {
                    float4 tmp = *reinterpret_cast<const float4 *>(&poolS[(q * 32 + p) * 68 + k]);
                    av[q][0] = tmp.x; av[q][1] = tmp.y; av[q][2] = tmp.z; av[q][3] = tmp.w;
                }
#pragma unroll
                for (int kk = 0; kk < 4; kk++) {
                    float4 wlo = *reinterpret_cast<const float4 *>(&W1T[(k + kk) * 64 + h0]);
                    float4 whi = *reinterpret_cast<const float4 *>(&W1T[(k + kk) * 64 + h0 + 4]);
                    float2 w0 = make_float2(wlo.x, wlo.y);
                    float2 w1 = make_float2(wlo.z, wlo.w);
                    float2 w2 = make_float2(whi.x, whi.y);
                    float2 w3 = make_float2(whi.z, whi.w);
#pragma unroll
                    for (int q = 0; q < 4; q++) {
                        float a = av[q][kk];
                        fma2(acc[q][0], a, w0);
                        fma2(acc[q][1], a, w1);
                        fma2(acc[q][2], a, w2);
                        fma2(acc[q][3], a, w3);
                    }
                }
            }
#pragma unroll
            for (int q = 0; q < 4; q++) {
                int row = q * 32 + p;
                float v[8];
#pragma unroll
                for (int i = 0; i < 8; i++) {
                    float hv = (i & 1) ? acc[q][i >> 1].y : acc[q][i >> 1].x;
                    v[i] = fmaxf(hv + bo1S[h0 + i], 0.f);
                }
                *reinterpret_cast<float4 *>(&y1S[row * 68 + h0]) = make_float4(v[0], v[1], v[2], v[3]);
                *reinterpret_cast<float4 *>(&y1S[row * 68 + h0 + 4]) = make_float4(v[4], v[5], v[6], v[7]);
            }
        }
        __syncthreads();

#pragma unroll
        for (int half = 0; half < 2; half++) {
            int o0 = h0 + 64 * half;
            float2 acc[4][4];
#pragma unroll
            for (int q = 0; q < 4; q++)
#pragma unroll
                for (int j = 0; j < 4; j++) acc[q][j] = make_float2(0.f, 0.f);
#pragma unroll
            for (int k = 0; k < 64; k += 4) {
                float av[4][4];
#pragma unroll
                for (int q = 0; q < 4; q++) {
                    float4 tmp = *reinterpret_cast<const float4 *>(&y1S[(q * 32 + p) * 68 + k]);
                    av[q][0] = tmp.x; av[q][1] = tmp.y; av[q][2] = tmp.z; av[q][3] = tmp.w;
                }
#pragma unroll
                for (int kk = 0; kk < 4; kk++) {
                    float4 wlo = *reinterpret_cast<const float4 *>(&W2T[(k + kk) * 128 + o0]);
                    float4 whi = *reinterpret_cast<const float4 *>(&W2T[(k + kk) * 128 + o0 + 4]);
                    float2 w0 = make_float2(wlo.x, wlo.y);
                    float2 w1 = make_float2(wlo.z, wlo.w);
                    float2 w2 = make_float2(whi.x, whi.y);
                    float2 w3 = make_float2(whi.z, whi.w);
#pragma unroll
                    for (int q = 0; q < 4; q++) {
                        float a = av[q][kk];
                        fma2(acc[q][0], a, w0);
                        fma2(acc[q][1], a, w1);
                        fma2(acc[q][2], a, w2);
                        fma2(acc[q][3], a, w3);
                    }
                }
            }
#pragma unroll
            for (int q = 0; q < 4; q++) {
                int row = q * 32 + p;
                float vf = g_valid[bn0 + row] ? 1.f : 0.f;
                float v[8];
#pragma unroll
                for (int i = 0; i < 8; i++) {
                    float hv = (i & 1) ? acc[q][i >> 1].y : acc[q][i >> 1].x;
                    v[i] = (hv + bo2S[o0 + i]) * vf;
                }
                size_t base = (size_t)(bn0 + row) * 128 + o0;
                *reinterpret_cast<float4 *>(&out[base]) = make_float4(v[0], v[1], v[2], v[3]);
                *reinterpret_cast<float4 *>(&out[base + 4]) = make_float4(v[4], v[5], v[6], v[7]);
            }
        }
        __syncthreads();
    }
}

// ---------------- launcher ----------------
extern "C" void kernel_launch(void *const *d_in, const int *in_sizes, int n_in,
                              void *d_out, int out_size) {
    const float *poly = (const float *)d_in[0];
    const void *mask = d_in[1];
    const float *Wpre = (const float *)d_in[2];
    const float *gpre = (const float *)d_in[3];
    const float *bpre = (const float *)d_in[4];
    const float *W1 = (const float *)d_in[5];
    const float *g1 = (const float *)d_in[6];
    const float *b1 = (const float *)d_in[7];
    const float *W2 = (const float *)d_in[8];
    const float *g2 = (const float *)d_in[9];
    const float *b2 = (const float *)d_in[10];
    const float *Wo1 = (const float *)d_in[11];
    const float *bo1 = (const float *)d_in[12];
    const float *Wo2 = (const float *)d_in[13];
    const float *bo2 = (const float *)d_in[14];
    float *out = (float *)d_out;

    cudaFuncSetAttribute(k_mlp1, cudaFuncAttributeMaxDynamicSharedMemorySize, 72704);
    cudaFuncSetAttribute(k_mlp2, cudaFuncAttributeMaxDynamicSharedMemorySize, 37888);
    cudaFuncSetAttribute(k_out,  cudaFuncAttributeMaxDynamicSharedMemorySize, 120064);

    k_init<<<1, 256>>>((const unsigned char *)mask);                 // idx 0
    k_pre<<<6144, 256>>>(poly, Wpre, mask);                          // idx 1
    k_mlp1<<<6144, 256, 72704>>>(poly, Wpre, gpre, bpre, W1);        // idx 2
    k_mlp2<<<6144, 256, 37888>>>(g1, b1, W2);                        // idx 3  <- profiled
    k_out<<<96, 256, 120064>>>(g2, b2, Wo1, bo1, Wo2, bo2, out);     // idx 4
}